// round 8
// baseline (speedup 1.0000x reference)
#include <cuda_runtime.h>
#include <math.h>

#define BHN  16
#define SEQ  2048
#define DIM  64
#define BM   128     // query rows per CTA (16 per warp, 8 warps)
#define BN   64      // key cols per tile
#define NTHR 256

#define QSTR 68      // bank = 4*row + col  bijection for 8x4 fragment cells
#define KSTR 68
#define VSTR 72      // bank = 8*k + n      bijection for 4x8 fragment cells

#define QTILE (BM * QSTR)
#define KTILE (BN * KSTR)
#define VTILE (BN * VSTR)
#define SMEM_FLOATS (2 * QTILE + 2 * KTILE + 2 * VTILE)

__device__ __forceinline__ unsigned f2tf(float f) {
    unsigned u;
    asm("cvt.rna.tf32.f32 %0, %1;" : "=r"(u) : "f"(f));
    return u;
}

__device__ __forceinline__ void mma_tf32(float c[4],
                                         unsigned a0, unsigned a1, unsigned a2, unsigned a3,
                                         unsigned b0, unsigned b1) {
    asm volatile(
        "mma.sync.aligned.m16n8k8.row.col.f32.tf32.tf32.f32 "
        "{%0,%1,%2,%3}, {%4,%5,%6,%7}, {%8,%9}, {%0,%1,%2,%3};"
        : "+f"(c[0]), "+f"(c[1]), "+f"(c[2]), "+f"(c[3])
        : "r"(a0), "r"(a1), "r"(a2), "r"(a3), "r"(b0), "r"(b1));
}

__global__ __launch_bounds__(NTHR, 1)
void attn_dual_mma(const float* __restrict__ Qx, const float* __restrict__ Kx,
                   const float* __restrict__ Vx, const float* __restrict__ Qy,
                   const float* __restrict__ Ky, const float* __restrict__ Vy,
                   float* __restrict__ O1, float* __restrict__ O2)
{
    extern __shared__ float smem[];
    float* sqx = smem;
    float* sqy = sqx + QTILE;
    float* skx = sqy + QTILE;
    float* sky = skx + KTILE;
    float* svx = sky + KTILE;
    float* svy = svx + VTILE;

    unsigned* uqx = (unsigned*)sqx;
    unsigned* uqy = (unsigned*)sqy;
    unsigned* ukx = (unsigned*)skx;
    unsigned* uky = (unsigned*)sky;
    unsigned* uvx = (unsigned*)svx;
    unsigned* uvy = (unsigned*)svy;

    const int tid  = threadIdx.x;
    const int warp = tid >> 5;
    const int lane = tid & 31;
    const int g    = lane >> 2;   // 0..7
    const int t    = lane & 3;    // 0..3
    const int bh   = blockIdx.y;
    const int qt   = blockIdx.x;

    const size_t head_off = (size_t)bh * SEQ * DIM;
    const float* qxg = Qx + head_off + (size_t)qt * BM * DIM;
    const float* qyg = Qy + head_off + (size_t)qt * BM * DIM;

    const float scale = 0.0625f;  // 0.5 * 1/sqrt(64), folded into Q

    // ---- Load Q once (scale + tf32 round) ----
    #pragma unroll
    for (int it = 0; it < BM * (DIM / 4) / NTHR; it++) {
        int idx = it * NTHR + tid;
        int m  = idx >> 4;
        int d4 = (idx & 15) << 2;
        float4 a = *(const float4*)(qxg + m * DIM + d4);
        float4 b = *(const float4*)(qyg + m * DIM + d4);
        uint4 ua = make_uint4(f2tf(a.x * scale), f2tf(a.y * scale),
                              f2tf(a.z * scale), f2tf(a.w * scale));
        uint4 ub = make_uint4(f2tf(b.x * scale), f2tf(b.y * scale),
                              f2tf(b.z * scale), f2tf(b.w * scale));
        *(uint4*)&uqx[m * QSTR + d4] = ua;
        *(uint4*)&uqy[m * QSTR + d4] = ub;
    }

    // ---- Flash state: warp owns rows [16*warp, 16*warp+16) ----
    const int r0 = warp * 16 + g;   // smem row for c0/c1
    const int r1 = r0 + 8;          // smem row for c2/c3

    float o1[8][4], o2[8][4];
    #pragma unroll
    for (int nt = 0; nt < 8; nt++)
        #pragma unroll
        for (int j = 0; j < 4; j++) { o1[nt][j] = 0.0f; o2[nt][j] = 0.0f; }
    float mr0 = -INFINITY, mr1 = -INFINITY, l0 = 0.0f, l1 = 0.0f;

    const int src0 = (lane & ~3) | (t >> 1);   // source lane for P cols 0..3
    const int src1 = src0 | 2;                 // source lane for P cols 4..7
    const bool odd = (t & 1);

    for (int kt = 0; kt < SEQ / BN; kt++) {
        const float* kxg = Kx + head_off + (size_t)kt * BN * DIM;
        const float* kyg = Ky + head_off + (size_t)kt * BN * DIM;
        const float* vxg = Vx + head_off + (size_t)kt * BN * DIM;
        const float* vyg = Vy + head_off + (size_t)kt * BN * DIM;

        // ---- Load K, V tiles (tf32 round) ----
        #pragma unroll
        for (int it = 0; it < BN * (DIM / 4) / NTHR; it++) {
            int idx = it * NTHR + tid;
            int n  = idx >> 4;
            int d4 = (idx & 15) << 2;
            float4 a = *(const float4*)(kxg + n * DIM + d4);
            float4 b = *(const float4*)(kyg + n * DIM + d4);
            float4 c = *(const float4*)(vxg + n * DIM + d4);
            float4 d = *(const float4*)(vyg + n * DIM + d4);
            *(uint4*)&ukx[n * KSTR + d4] =
                make_uint4(f2tf(a.x), f2tf(a.y), f2tf(a.z), f2tf(a.w));
            *(uint4*)&uky[n * KSTR + d4] =
                make_uint4(f2tf(b.x), f2tf(b.y), f2tf(b.z), f2tf(b.w));
            *(uint4*)&uvx[n * VSTR + d4] =
                make_uint4(f2tf(c.x), f2tf(c.y), f2tf(c.z), f2tf(c.w));
            *(uint4*)&uvy[n * VSTR + d4] =
                make_uint4(f2tf(d.x), f2tf(d.y), f2tf(d.z), f2tf(d.w));
        }
        __syncthreads();

        // ---- S = (Qx Kx^T + Qy Ky^T) * scale  via tf32 MMA ----
        float sacc[8][4];
        #pragma unroll
        for (int nt = 0; nt < 8; nt++)
            #pragma unroll
            for (int j = 0; j < 4; j++) sacc[nt][j] = 0.0f;

        #pragma unroll
        for (int ks = 0; ks < 8; ks++) {
            int c0 = ks * 8 + t;
            unsigned ax0 = uqx[r0 * QSTR + c0];
            unsigned ax1 = uqx[r1 * QSTR + c0];
            unsigned ax2 = uqx[r0 * QSTR + c0 + 4];
            unsigned ax3 = uqx[r1 * QSTR + c0 + 4];
            unsigned ay0 = uqy[r0 * QSTR + c0];
            unsigned ay1 = uqy[r1 * QSTR + c0];
            unsigned ay2 = uqy[r0 * QSTR + c0 + 4];
            unsigned ay3 = uqy[r1 * QSTR + c0 + 4];
            #pragma unroll
            for (int nt = 0; nt < 8; nt++) {
                int bn = (nt * 8 + g) * KSTR + c0;
                mma_tf32(sacc[nt], ax0, ax1, ax2, ax3, ukx[bn], ukx[bn + 4]);
                mma_tf32(sacc[nt], ay0, ay1, ay2, ay3, uky[bn], uky[bn + 4]);
            }
        }

        // ---- Online softmax (rows r0, r1 per lane; quad shuffles complete rows) ----
        float rmax0 = -INFINITY, rmax1 = -INFINITY;
        #pragma unroll
        for (int nt = 0; nt < 8; nt++) {
            rmax0 = fmaxf(rmax0, fmaxf(sacc[nt][0], sacc[nt][1]));
            rmax1 = fmaxf(rmax1, fmaxf(sacc[nt][2], sacc[nt][3]));
        }
        rmax0 = fmaxf(rmax0, __shfl_xor_sync(0xffffffffu, rmax0, 1));
        rmax0 = fmaxf(rmax0, __shfl_xor_sync(0xffffffffu, rmax0, 2));
        rmax1 = fmaxf(rmax1, __shfl_xor_sync(0xffffffffu, rmax1, 1));
        rmax1 = fmaxf(rmax1, __shfl_xor_sync(0xffffffffu, rmax1, 2));

        float mn0 = fmaxf(mr0, rmax0);
        float mn1 = fmaxf(mr1, rmax1);
        float al0 = __expf(mr0 - mn0);
        float al1 = __expf(mr1 - mn1);

        unsigned p[8][4];
        float rs0 = 0.0f, rs1 = 0.0f;
        #pragma unroll
        for (int nt = 0; nt < 8; nt++) {
            float p0 = __expf(sacc[nt][0] - mn0);
            float p1 = __expf(sacc[nt][1] - mn0);
            float p2 = __expf(sacc[nt][2] - mn1);
            float p3 = __expf(sacc[nt][3] - mn1);
            rs0 += p0 + p1;
            rs1 += p2 + p3;
            p[nt][0] = f2tf(p0); p[nt][1] = f2tf(p1);
            p[nt][2] = f2tf(p2); p[nt][3] = f2tf(p3);
        }
        rs0 += __shfl_xor_sync(0xffffffffu, rs0, 1);
        rs0 += __shfl_xor_sync(0xffffffffu, rs0, 2);
        rs1 += __shfl_xor_sync(0xffffffffu, rs1, 1);
        rs1 += __shfl_xor_sync(0xffffffffu, rs1, 2);

        l0 = l0 * al0 + rs0;
        l1 = l1 * al1 + rs1;
        mr0 = mn0;
        mr1 = mn1;

        #pragma unroll
        for (int nt = 0; nt < 8; nt++) {
            o1[nt][0] *= al0; o1[nt][1] *= al0; o1[nt][2] *= al1; o1[nt][3] *= al1;
            o2[nt][0] *= al0; o2[nt][1] *= al0; o2[nt][2] *= al1; o2[nt][3] *= al1;
        }

        // ---- O += P @ V  (P: D-frag -> A-frag via quad shuffles) ----
        #pragma unroll
        for (int kc = 0; kc < 8; kc++) {
            unsigned q0, q1;
            q0 = __shfl_sync(0xffffffffu, p[kc][0], src0);
            q1 = __shfl_sync(0xffffffffu, p[kc][1], src0);
            unsigned pa0 = odd ? q1 : q0;
            q0 = __shfl_sync(0xffffffffu, p[kc][2], src0);
            q1 = __shfl_sync(0xffffffffu, p[kc][3], src0);
            unsigned pa1 = odd ? q1 : q0;
            q0 = __shfl_sync(0xffffffffu, p[kc][0], src1);
            q1 = __shfl_sync(0xffffffffu, p[kc][1], src1);
            unsigned pa2 = odd ? q1 : q0;
            q0 = __shfl_sync(0xffffffffu, p[kc][2], src1);
            q1 = __shfl_sync(0xffffffffu, p[kc][3], src1);
            unsigned pa3 = odd ? q1 : q0;

            int kb = (kc * 8 + t) * VSTR;
            #pragma unroll
            for (int nt = 0; nt < 8; nt++) {
                int nn = nt * 8 + g;
                mma_tf32(o1[nt], pa0, pa1, pa2, pa3,
                         uvx[kb + nn], uvx[kb + 4 * VSTR + nn]);
                mma_tf32(o2[nt], pa0, pa1, pa2, pa3,
                         uvy[kb + nn], uvy[kb + 4 * VSTR + nn]);
            }
        }
        __syncthreads();   // K/V smem reused next tile
    }

    // ---- Epilogue: normalize, store ----
    float inv0 = 1.0f / l0;
    float inv1 = 1.0f / l1;
    const size_t row_g0 = (size_t)qt * BM + warp * 16 + g;
    const size_t row_g1 = row_g0 + 8;
    float* o1a = O1 + head_off + row_g0 * DIM;
    float* o1b = O1 + head_off + row_g1 * DIM;
    float* o2a = O2 + head_off + row_g0 * DIM;
    float* o2b = O2 + head_off + row_g1 * DIM;
    #pragma unroll
    for (int nt = 0; nt < 8; nt++) {
        int col = nt * 8 + 2 * t;
        *(float2*)&o1a[col] = make_float2(o1[nt][0] * inv0, o1[nt][1] * inv0);
        *(float2*)&o1b[col] = make_float2(o1[nt][2] * inv1, o1[nt][3] * inv1);
        *(float2*)&o2a[col] = make_float2(o2[nt][0] * inv0, o2[nt][1] * inv0);
        *(float2*)&o2b[col] = make_float2(o2[nt][2] * inv1, o2[nt][3] * inv1);
    }
}

extern "C" void kernel_launch(void* const* d_in, const int* in_sizes, int n_in,
                              void* d_out, int out_size)
{
    const float* Qx = (const float*)d_in[0];
    const float* Kx = (const float*)d_in[1];
    const float* Vx = (const float*)d_in[2];
    const float* Qy = (const float*)d_in[3];
    const float* Ky = (const float*)d_in[4];
    const float* Vy = (const float*)d_in[5];
    float* O1 = (float*)d_out;
    float* O2 = (float*)d_out + (size_t)BHN * SEQ * DIM;

    size_t smem_bytes = SMEM_FLOATS * sizeof(float);
    cudaFuncSetAttribute(attn_dual_mma,
                         cudaFuncAttributeMaxDynamicSharedMemorySize,
                         (int)smem_bytes);

    dim3 grid(SEQ / BM, BHN);
    attn_dual_mma<<<grid, NTHR, smem_bytes>>>(Qx, Kx, Vx, Qy, Ky, Vy, O1, O2);
}